// round 6
// baseline (speedup 1.0000x reference)
#include <cuda_runtime.h>
#include <math.h>

#define D        128
#define MAX_ENT  100000
#define MAX_EDG  200000

// ---------------- scratch (device globals: no allocations allowed) ----------
__device__ float g_Xl[(size_t)MAX_ENT * D];   // lorentz_linear(emb_E)
__device__ float g_Xe[(size_t)MAX_EDG * D];   // segment_sum over edges
__device__ float g_Xv[(size_t)MAX_ENT * D];   // segment_sum over vertex (needed rows only)
__device__ int   g_flag[MAX_ENT];             // vertex needed by e1..e6 gather?

// ---------------- kernel 0: zero scratch ------------------------------------
__global__ void k_zero(int nent, int nedg)
{
    size_t ne4 = (size_t)nedg * (D / 4);
    size_t nv4 = (size_t)nent * (D / 4);
    size_t tot = ne4 + nv4;
    size_t i = (size_t)blockIdx.x * blockDim.x + threadIdx.x;
    size_t stride = (size_t)gridDim.x * blockDim.x;
    float4 z = make_float4(0.f, 0.f, 0.f, 0.f);
    float4* pe = reinterpret_cast<float4*>(g_Xe);
    float4* pv = reinterpret_cast<float4*>(g_Xv);
    for (size_t j = i; j < tot; j += stride) {
        if (j < ne4) pe[j] = z;
        else         pv[j - ne4] = z;
    }
    for (size_t j = i; j < (size_t)nent; j += stride) g_flag[j] = 0;
}

// ---------------- kernel 1: mark needed vertices ----------------------------
__global__ void k_flags(const int* __restrict__ e1, const int* __restrict__ e2,
                        const int* __restrict__ e3, const int* __restrict__ e4,
                        const int* __restrict__ e5, const int* __restrict__ e6,
                        int batch)
{
    int i = blockIdx.x * blockDim.x + threadIdx.x;
    if (i >= batch) return;
    g_flag[e1[i]] = 1;
    g_flag[e2[i]] = 1;
    g_flag[e3[i]] = 1;
    g_flag[e4[i]] = 1;
    g_flag[e5[i]] = 1;
    g_flag[e6[i]] = 1;
}

// ---------------- kernel 2: Xl = lorentz_linear(emb_E) ----------------------
// x = emb @ W^T + b ; time = sigmoid(x0)*exp(scale)+1.1 ;
// s = sqrt((time^2-1)/max(sum(x[1:]^2),1e-8)) ; Xl = [time, x[1:]*s]
// Block: 128 threads (thread = output column j), 64 rows per block, 8 rows/pass.
// W held transposed+padded in dynamic smem (conflict-free).
__global__ void k_gemm_lorentz(const float* __restrict__ emb,
                               const float* __restrict__ W,
                               const float* __restrict__ bvec,
                               const float* __restrict__ scale_p,
                               int nrows)
{
    extern __shared__ float Wt[];              // [128 * 129]
    __shared__ __align__(16) float Es[8][D];
    __shared__ float sred[8][4];
    __shared__ float sx0[8];

    const int tid  = threadIdx.x;              // 0..127 == output column j
    const int lane = tid & 31;
    const int warp = tid >> 5;

    // Wt[k*129 + j] = W[j*D + k]; here k = tid, j = n  (coalesced gld, cf-free sts)
    for (int n = 0; n < D; n++)
        Wt[tid * 129 + n] = W[n * D + tid];

    const float bj       = bvec[tid];
    const float expscale = expf(scale_p[0]);
    __syncthreads();

    const int row0 = blockIdx.x * 64;
    for (int rr = 0; rr < 64; rr += 8) {
        const int rbase = row0 + rr;
        #pragma unroll
        for (int i = 0; i < 8; i++) {
            int r = rbase + i;
            Es[i][tid] = (r < nrows) ? emb[(size_t)r * D + tid] : 0.0f;
        }
        __syncthreads();

        float acc[8];
        #pragma unroll
        for (int i = 0; i < 8; i++) acc[i] = bj;

        #pragma unroll 8
        for (int k = 0; k < D; k += 4) {
            float w0 = Wt[(k + 0) * 129 + tid];
            float w1 = Wt[(k + 1) * 129 + tid];
            float w2 = Wt[(k + 2) * 129 + tid];
            float w3 = Wt[(k + 3) * 129 + tid];
            #pragma unroll
            for (int i = 0; i < 8; i++) {
                float4 e = *reinterpret_cast<const float4*>(&Es[i][k]);
                acc[i] = fmaf(e.x, w0, acc[i]);
                acc[i] = fmaf(e.y, w1, acc[i]);
                acc[i] = fmaf(e.z, w2, acc[i]);
                acc[i] = fmaf(e.w, w3, acc[i]);
            }
        }

        // per-row reduction of x[1:]^2 ; capture x0 (thread 0 holds column 0)
        float part[8];
        #pragma unroll
        for (int i = 0; i < 8; i++) part[i] = (tid == 0) ? 0.0f : acc[i] * acc[i];
        #pragma unroll
        for (int off = 16; off; off >>= 1) {
            #pragma unroll
            for (int i = 0; i < 8; i++)
                part[i] += __shfl_xor_sync(0xffffffffu, part[i], off);
        }
        if (lane == 0) {
            #pragma unroll
            for (int i = 0; i < 8; i++) sred[i][warp] = part[i];
        }
        if (tid == 0) {
            #pragma unroll
            for (int i = 0; i < 8; i++) sx0[i] = acc[i];
        }
        __syncthreads();

        #pragma unroll
        for (int i = 0; i < 8; i++) {
            int r = rbase + i;
            if (r >= nrows) continue;
            float sq   = sred[i][0] + sred[i][1] + sred[i][2] + sred[i][3];
            float x0   = sx0[i];
            float timev = expscale / (1.0f + expf(-x0)) + 1.1f;
            float s    = sqrtf((timev * timev - 1.0f) / fmaxf(sq, 1e-8f));
            g_Xl[(size_t)r * D + tid] = (tid == 0) ? timev : acc[i] * s;
        }
        __syncthreads();
    }
}

// ---------------- kernel 3: Xe += scatter(Xl[vertex] - emb_ty[ty]) ----------
// one warp per nnz entry; lane handles 4 floats; 128-bit vector reduction.
__global__ void k_scatterA(const int* __restrict__ vertex, const int* __restrict__ edges,
                           const int* __restrict__ ty, const float* __restrict__ emb_ty,
                           int nnz)
{
    int w    = (blockIdx.x * blockDim.x + threadIdx.x) >> 5;
    int lane = threadIdx.x & 31;
    if (w >= nnz) return;
    int v = __ldg(&vertex[w]);
    int e = __ldg(&edges[w]);
    int t = __ldg(&ty[w]);
    float4 a  = reinterpret_cast<const float4*>(g_Xl   + (size_t)v * D)[lane];
    float4 bb = reinterpret_cast<const float4*>(emb_ty + (size_t)t * D)[lane];
    float* dst = g_Xe + (size_t)e * D + lane * 4;
    asm volatile("red.global.add.v4.f32 [%0], {%1, %2, %3, %4};"
                 :: "l"(dst), "f"(a.x - bb.x), "f"(a.y - bb.y),
                    "f"(a.z - bb.z), "f"(a.w - bb.w)
                 : "memory");
}

// ---------------- kernel 4: Xv += scatter(Xe[edges]) for needed vertices ----
__global__ void k_scatterB(const int* __restrict__ vertex, const int* __restrict__ edges,
                           int nnz)
{
    int w    = (blockIdx.x * blockDim.x + threadIdx.x) >> 5;
    int lane = threadIdx.x & 31;
    if (w >= nnz) return;
    int v = __ldg(&vertex[w]);
    if (!g_flag[v]) return;                 // ~75% of nnz skipped
    int e = __ldg(&edges[w]);
    float4 a = reinterpret_cast<const float4*>(g_Xe + (size_t)e * D)[lane];
    float* dst = g_Xv + (size_t)v * D + lane * 4;
    asm volatile("red.global.add.v4.f32 [%0], {%1, %2, %3, %4};"
                 :: "l"(dst), "f"(a.x), "f"(a.y), "f"(a.z), "f"(a.w)
                 : "memory");
}

// ---------------- kernel 5: fused logmap0 + 6-way gather product + rowsum ---
// E_e[i] = logmap0(eps*Xv[i] + Xl[i]); E_e[0] := 1; R_e[0] := 1;
// out[b] = sum_d prod_k E_e[ek[b]][d] * R_e[r_idx[b]][d]
__global__ void k_final(const float* __restrict__ emb_R, const float* __restrict__ epsp,
                        const int* __restrict__ r_idx,
                        const int* __restrict__ e1, const int* __restrict__ e2,
                        const int* __restrict__ e3, const int* __restrict__ e4,
                        const int* __restrict__ e5, const int* __restrict__ e6,
                        float* __restrict__ out)
{
    const int b    = blockIdx.x;
    const int tid  = threadIdx.x;
    const int lane = tid & 31;
    const int warp = tid >> 5;
    __shared__ float sred[4];
    __shared__ float sx0;

    const float eps = epsp[0];
    const int ri = r_idx[b];
    float prod = (ri == 0) ? 1.0f : emb_R[(size_t)ri * D + tid];

    const int* es[6] = {e1, e2, e3, e4, e5, e6};
    #pragma unroll
    for (int k = 0; k < 6; k++) {
        int idx = es[k][b];               // uniform per block
        float Ed;
        if (idx == 0) {
            Ed = 1.0f;                    // E_e.at[0].set(1.0)
        } else {
            float v = eps * g_Xv[(size_t)idx * D + tid] + g_Xl[(size_t)idx * D + tid];
            float p = (tid == 0) ? 0.0f : v * v;
            #pragma unroll
            for (int off = 16; off; off >>= 1)
                p += __shfl_xor_sync(0xffffffffu, p, off);
            if (lane == 0) sred[warp] = p;
            if (tid == 0)  sx0 = v;
            __syncthreads();
            float sq    = sred[0] + sred[1] + sred[2] + sred[3];
            float ynorm = fmaxf(sqrtf(sq), 1e-8f);
            float theta = fmaxf(sx0, 1.0f + 1e-7f);
            float coef  = acoshf(theta) / ynorm;
            Ed = (tid == 0) ? 0.0f : coef * v;
            __syncthreads();              // protect sred/sx0 reuse
        }
        prod *= Ed;
    }

    float s = prod;
    #pragma unroll
    for (int off = 16; off; off >>= 1)
        s += __shfl_xor_sync(0xffffffffu, s, off);
    if (lane == 0) sred[warp] = s;
    __syncthreads();
    if (tid == 0) out[b] = sred[0] + sred[1] + sred[2] + sred[3];
}

// ---------------- launch ----------------------------------------------------
extern "C" void kernel_launch(void* const* d_in, const int* in_sizes, int n_in,
                              void* d_out, int out_size)
{
    const float* emb_E     = (const float*)d_in[0];
    const float* emb_R     = (const float*)d_in[1];
    const float* emb_ty    = (const float*)d_in[2];
    const float* lin_W     = (const float*)d_in[3];
    const float* lin_b     = (const float*)d_in[4];
    const float* lin_scale = (const float*)d_in[5];
    const float* eps       = (const float*)d_in[6];
    // d_in[7] = ms (unused by reference)
    const int* r_idx = (const int*)d_in[8];
    const int* e1    = (const int*)d_in[9];
    const int* e2    = (const int*)d_in[10];
    const int* e3    = (const int*)d_in[11];
    const int* e4    = (const int*)d_in[12];
    const int* e5    = (const int*)d_in[13];
    const int* e6    = (const int*)d_in[14];
    const int* vertex = (const int*)d_in[15];
    const int* edges  = (const int*)d_in[16];
    const int* ty     = (const int*)d_in[17];

    const int batch = in_sizes[8];
    const int nnz   = in_sizes[15];
    const int nent  = in_sizes[0] / D;
    const int nedg  = MAX_EDG;
    float* out = (float*)d_out;

    // 0) zero scratch + flags
    k_zero<<<2048, 256>>>(nent, nedg);

    // 1) mark needed vertices
    k_flags<<<(batch + 255) / 256, 256>>>(e1, e2, e3, e4, e5, e6, batch);

    // 2) GEMM + lorentz_linear (66 KB dynamic smem for padded W^T)
    const int wt_bytes = 128 * 129 * (int)sizeof(float);
    cudaFuncSetAttribute(k_gemm_lorentz,
                         cudaFuncAttributeMaxDynamicSharedMemorySize, wt_bytes);
    k_gemm_lorentz<<<(nent + 63) / 64, 128, wt_bytes>>>(emb_E, lin_W, lin_b,
                                                        lin_scale, nent);

    // 3) + 4) the two segment-sum scatters (one warp per nnz entry)
    int sgrid = (nnz + 7) / 8;   // 8 warps / 256-thread block
    k_scatterA<<<sgrid, 256>>>(vertex, edges, ty, emb_ty, nnz);
    k_scatterB<<<sgrid, 256>>>(vertex, edges, nnz);

    // 5) fused epilogue: one block per batch element
    k_final<<<batch, 128>>>(emb_R, eps, r_idx, e1, e2, e3, e4, e5, e6, out);
}